// round 15
// baseline (speedup 1.0000x reference)
#include <cuda_runtime.h>
#include <cstdint>
#include <math.h>

#define Bb 16
#define Nn 128
#define DZ 128
#define DS 256
#define Hh 8
#define HDIM 32
#define BI (Bb*Nn)
#define INV_SCALE 0.17677669529663687f
#define LN_EPS 1e-5f
#define ZP 132

// ---------------- scratch ----------------
__device__ __align__(16) float g_Q   [BI*DS];
__device__ __align__(16) float g_QKG [BI*Hh*DZ];
__device__ __align__(16) float g_CTX [BI*Hh*DZ];
__device__ __align__(16) float g_OUTS[BI*DS];
__device__ __align__(16) float g_wkb [DS];
__device__ __align__(16) float g_Wk2 [Hh*DZ*HDIM];   // [o=h*128+d][e]
__device__ __align__(16) float g_A1  [DS];           // sum_c gs[c]*wq[o][c]
__device__ __align__(16) float g_B1  [DS];           // sum_c bs[c]*wq[o][c] + bq[o]

__device__ __forceinline__ unsigned f2tf(float x) {
    unsigned r; asm("cvt.rna.tf32.f32 %0, %1;" : "=r"(r) : "f"(x)); return r;
}
__device__ __forceinline__ uint4 tf4(float4 v) {
    return make_uint4(f2tf(v.x), f2tf(v.y), f2tf(v.z), f2tf(v.w));
}
__device__ __forceinline__ void mma_tf32(float* c, const unsigned* a, unsigned b0, unsigned b1) {
    asm volatile(
        "mma.sync.aligned.m16n8k8.row.col.f32.tf32.tf32.f32 "
        "{%0,%1,%2,%3}, {%4,%5,%6,%7}, {%8,%9}, {%0,%1,%2,%3};"
        : "+f"(c[0]), "+f"(c[1]), "+f"(c[2]), "+f"(c[3])
        : "r"(a[0]), "r"(a[1]), "r"(a[2]), "r"(a[3]), "r"(b0), "r"(b1));
}
__device__ __forceinline__ void cp16(unsigned int dst, const void* src) {
    asm volatile("cp.async.cg.shared.global [%0], [%1], 16;\n" :: "r"(dst), "l"(src));
}

// ---------------- pre: weight prep only (130 blocks) ----------------
__global__ void pre_kernel(const float* __restrict__ wk, const float* __restrict__ bk,
                           const float* __restrict__ bz, const float* __restrict__ gz,
                           const float* __restrict__ wq, const float* __restrict__ bq,
                           const float* __restrict__ gs, const float* __restrict__ bs) {
    int t = threadIdx.x;
    if (blockIdx.x < 128) {
        int idx = blockIdx.x * 256 + t;
        int o = idx >> 5, e = idx & 31;
        int h = o >> 7,  d = o & 127;
        g_Wk2[idx] = wk[(size_t)(h*HDIM + e)*DZ + d] * gz[d] * INV_SCALE;
        if (blockIdx.x == 0) {
            int w = t >> 5, l = t & 31;
            for (int r = w; r < DS; r += 8) {
                float a = 0.f;
                #pragma unroll
                for (int k = 0; k < 4; k++) { int dd = l + 32*k; a += wk[(size_t)r*DZ + dd] * bz[dd]; }
                #pragma unroll
                for (int oo = 16; oo > 0; oo >>= 1) a += __shfl_xor_sync(0xffffffffu, a, oo);
                if (l == 0) g_wkb[r] = a + bk[r];
            }
        }
    } else {
        // A1/B1: thread t handles output row o=t
        float a1 = 0.f, b1 = 0.f;
        const float* wr = &wq[(size_t)t*DS];
        for (int c = 0; c < DS; c++) {
            float wv = wr[c];
            a1 += gs[c] * wv;
            b1 += bs[c] * wv;
        }
        g_A1[t] = a1;
        g_B1[t] = b1 + bq[t];
    }
}

// ---------------- gemm_q: LN(s) fused Q-projection ----------------
// Q[r][o] = rinv_r*(sum_c s[r][c]*gs[c]*wq[o][c]) - m_r*rinv_r*A1[o] + B1[o]
// BM=32, BN=64, WGM=2, WGN=4, K=256.
#define GQ_SMEM_FLOATS (2*32*36 + 2*64*36 + 64)
__global__ __launch_bounds__(256) void gemm_q(
        const float* __restrict__ S, const float* __restrict__ wq,
        const float* __restrict__ gs) {
    extern __shared__ float smem[];
    float* Asb = smem;                 // 2 x 32x36
    float* Bsb = smem + 2*32*36;       // 2 x 64x36
    float2* rowstats = reinterpret_cast<float2*>(smem + 2*32*36 + 2*64*36);  // 32 x float2

    int t = threadIdx.x, w = t >> 5, lane = t & 31;
    int gr = lane >> 2, gc = lane & 3;
    int wm = (w >> 2) * 16, wn = (w & 3) * 16;
    int r0 = blockIdx.y * 32, c0 = blockIdx.x * 64;

    int arow = t >> 3, ak4 = t & 7;    // A loader mapping (1 float4/thread/chunk)
    float acc[2][4];
    #pragma unroll
    for (int nf = 0; nf < 2; nf++)
        #pragma unroll
        for (int q = 0; q < 4; q++) acc[nf][q] = 0.f;

    float ssum = 0.f, ssq = 0.f;
    float4 ra, rb[2];

    // prologue chunk 0
    ra = *reinterpret_cast<const float4*>(&S[(size_t)(r0+arow)*DS + ak4*4]);
    ssum += ra.x + ra.y + ra.z + ra.w;
    ssq  += ra.x*ra.x + ra.y*ra.y + ra.z*ra.z + ra.w*ra.w;
    #pragma unroll
    for (int i = 0; i < 2; i++) {
        int idx = t + i*256; int row = idx >> 3, k4 = idx & 7;
        float4 v = *reinterpret_cast<const float4*>(&wq[(size_t)(c0+row)*DS + k4*4]);
        float4 g = *reinterpret_cast<const float4*>(&gs[k4*4]);
        rb[i] = make_float4(v.x*g.x, v.y*g.y, v.z*g.z, v.w*g.w);
    }
    *reinterpret_cast<uint4*>(&Asb[arow*36 + ak4*4]) = tf4(ra);
    #pragma unroll
    for (int i = 0; i < 2; i++) {
        int idx = t + i*256; int row = idx >> 3, k4 = idx & 7;
        *reinterpret_cast<uint4*>(&Bsb[row*36 + k4*4]) = tf4(rb[i]);
    }
    __syncthreads();

    for (int ch = 0; ch < 8; ch++) {
        int cur = ch & 1;
        const float* As = Asb + cur*32*36;
        const float* Bs = Bsb + cur*64*36;
        if (ch + 1 < 8) {
            int kc = (ch+1)*32;
            ra = *reinterpret_cast<const float4*>(&S[(size_t)(r0+arow)*DS + kc + ak4*4]);
            ssum += ra.x + ra.y + ra.z + ra.w;
            ssq  += ra.x*ra.x + ra.y*ra.y + ra.z*ra.z + ra.w*ra.w;
            #pragma unroll
            for (int i = 0; i < 2; i++) {
                int idx = t + i*256; int row = idx >> 3, k4 = idx & 7;
                float4 v = *reinterpret_cast<const float4*>(&wq[(size_t)(c0+row)*DS + kc + k4*4]);
                float4 g = *reinterpret_cast<const float4*>(&gs[kc + k4*4]);
                rb[i] = make_float4(v.x*g.x, v.y*g.y, v.z*g.z, v.w*g.w);
            }
        }
        #pragma unroll
        for (int ks = 0; ks < 4; ks++) {
            int ko = ks * 8;
            unsigned af[4];
            const float* ap = &As[(wm + gr)*36 + ko + gc];
            af[0] = __float_as_uint(ap[0]);
            af[1] = __float_as_uint(ap[8*36]);
            af[2] = __float_as_uint(ap[4]);
            af[3] = __float_as_uint(ap[8*36 + 4]);
            #pragma unroll
            for (int nf = 0; nf < 2; nf++) {
                const float* bp = &Bs[(wn + nf*8 + gr)*36 + ko + gc];
                unsigned b0 = __float_as_uint(bp[0]), b1 = __float_as_uint(bp[4]);
                mma_tf32(acc[nf], af, b0, b1);
            }
        }
        if (ch + 1 < 8) {
            int nxt = cur ^ 1;
            float* Asn = Asb + nxt*32*36;
            float* Bsn = Bsb + nxt*64*36;
            *reinterpret_cast<uint4*>(&Asn[arow*36 + ak4*4]) = tf4(ra);
            #pragma unroll
            for (int i = 0; i < 2; i++) {
                int idx = t + i*256; int row = idx >> 3, k4 = idx & 7;
                *reinterpret_cast<uint4*>(&Bsn[row*36 + k4*4]) = tf4(rb[i]);
            }
            __syncthreads();
        }
    }

    // row LN stats: reduce over the 8 lanes sharing a row
    #pragma unroll
    for (int o = 4; o > 0; o >>= 1) {
        ssum += __shfl_xor_sync(0xffffffffu, ssum, o);
        ssq  += __shfl_xor_sync(0xffffffffu, ssq,  o);
    }
    if ((lane & 7) == 0) {
        float m = ssum * (1.0f/DS);
        rowstats[arow] = make_float2(m, rsqrtf(ssq * (1.0f/DS) - m*m + LN_EPS));
    }
    __syncthreads();

    // epilogue with LN fold
    float2 st0 = rowstats[wm + gr];
    float2 st1 = rowstats[wm + gr + 8];
    #pragma unroll
    for (int nf = 0; nf < 2; nf++) {
        int col = c0 + wn + nf*8 + 2*gc;
        float a1x = g_A1[col], a1y = g_A1[col+1];
        float b1x = g_B1[col], b1y = g_B1[col+1];
        int row = r0 + wm + gr;
        float2 v0, v1;
        v0.x = st0.y*acc[nf][0] - st0.x*st0.y*a1x + b1x;
        v0.y = st0.y*acc[nf][1] - st0.x*st0.y*a1y + b1y;
        v1.x = st1.y*acc[nf][2] - st1.x*st1.y*a1x + b1x;
        v1.y = st1.y*acc[nf][3] - st1.x*st1.y*a1y + b1y;
        *reinterpret_cast<float2*>(&g_Q[(size_t)row*DS + col])     = v0;
        *reinterpret_cast<float2*>(&g_Q[(size_t)(row+8)*DS + col]) = v1;
    }
}

// ---------------- tf32 GEMM (R11 version) ----------------
template<int BM, int BN, int WGM, int WGN>
__global__ __launch_bounds__(256) void gemm_tc(
        const float* __restrict__ A, int lda,
        const float* __restrict__ B, int ldb,
        const float* __restrict__ bias,
        float* __restrict__ C, int ldc, int K,
        int head_cols, int ahs) {
    constexpr int TM = BM/WGM, TN = BN/WGN, MF = TM/16, NF = TN/8;
    constexpr int LA = BM*8/256;
    constexpr int LB = BN*8/256;
    extern __shared__ float smem[];
    float* Asb = smem;
    float* Bsb = smem + 2*BM*36;

    int t = threadIdx.x, w = t >> 5, lane = t & 31;
    int gr = lane >> 2, gc = lane & 3;
    int wm = (w / WGN) * TM, wn = (w % WGN) * TN;
    int r0 = blockIdx.y * BM, c0 = blockIdx.x * BN;
    int abase = (c0 / head_cols) * ahs;

    float acc[MF][NF][4];
    #pragma unroll
    for (int mf = 0; mf < MF; mf++)
        #pragma unroll
        for (int nf = 0; nf < NF; nf++)
            #pragma unroll
            for (int q = 0; q < 4; q++) acc[mf][nf][q] = 0.f;

    float4 ra[LA], rb[LB];
    #pragma unroll
    for (int i = 0; i < LA; i++) {
        int idx = t + i*256; int row = idx >> 3, k4 = idx & 7;
        ra[i] = *reinterpret_cast<const float4*>(&A[(size_t)(r0+row)*lda + abase + k4*4]);
    }
    #pragma unroll
    for (int i = 0; i < LB; i++) {
        int idx = t + i*256; int row = idx >> 3, k4 = idx & 7;
        rb[i] = *reinterpret_cast<const float4*>(&B[(size_t)(c0+row)*ldb + k4*4]);
    }
    #pragma unroll
    for (int i = 0; i < LA; i++) {
        int idx = t + i*256; int row = idx >> 3, k4 = idx & 7;
        *reinterpret_cast<uint4*>(&Asb[row*36 + k4*4]) = tf4(ra[i]);
    }
    #pragma unroll
    for (int i = 0; i < LB; i++) {
        int idx = t + i*256; int row = idx >> 3, k4 = idx & 7;
        *reinterpret_cast<uint4*>(&Bsb[row*36 + k4*4]) = tf4(rb[i]);
    }
    __syncthreads();

    int nch = K >> 5;
    for (int ch = 0; ch < nch; ch++) {
        int cur = ch & 1;
        const float* As = Asb + cur*BM*36;
        const float* Bs = Bsb + cur*BN*36;
        if (ch + 1 < nch) {
            int kc = (ch+1)*32;
            #pragma unroll
            for (int i = 0; i < LA; i++) {
                int idx = t + i*256; int row = idx >> 3, k4 = idx & 7;
                ra[i] = *reinterpret_cast<const float4*>(&A[(size_t)(r0+row)*lda + abase + kc + k4*4]);
            }
            #pragma unroll
            for (int i = 0; i < LB; i++) {
                int idx = t + i*256; int row = idx >> 3, k4 = idx & 7;
                rb[i] = *reinterpret_cast<const float4*>(&B[(size_t)(c0+row)*ldb + kc + k4*4]);
            }
        }
        #pragma unroll
        for (int ks = 0; ks < 4; ks++) {
            int ko = ks * 8;
            unsigned af[MF][4];
            #pragma unroll
            for (int mf = 0; mf < MF; mf++) {
                const float* ap = &As[(wm + mf*16 + gr)*36 + ko + gc];
                af[mf][0] = __float_as_uint(ap[0]);
                af[mf][1] = __float_as_uint(ap[8*36]);
                af[mf][2] = __float_as_uint(ap[4]);
                af[mf][3] = __float_as_uint(ap[8*36 + 4]);
            }
            #pragma unroll
            for (int nf = 0; nf < NF; nf++) {
                const float* bp = &Bs[(wn + nf*8 + gr)*36 + ko + gc];
                unsigned b0 = __float_as_uint(bp[0]), b1 = __float_as_uint(bp[4]);
                #pragma unroll
                for (int mf = 0; mf < MF; mf++)
                    mma_tf32(acc[mf][nf], af[mf], b0, b1);
            }
        }
        if (ch + 1 < nch) {
            int nxt = cur ^ 1;
            float* Asn = Asb + nxt*BM*36;
            float* Bsn = Bsb + nxt*BN*36;
            #pragma unroll
            for (int i = 0; i < LA; i++) {
                int idx = t + i*256; int row = idx >> 3, k4 = idx & 7;
                *reinterpret_cast<uint4*>(&Asn[row*36 + k4*4]) = tf4(ra[i]);
            }
            #pragma unroll
            for (int i = 0; i < LB; i++) {
                int idx = t + i*256; int row = idx >> 3, k4 = idx & 7;
                *reinterpret_cast<uint4*>(&Bsn[row*36 + k4*4]) = tf4(rb[i]);
            }
            __syncthreads();
        }
    }

    #pragma unroll
    for (int mf = 0; mf < MF; mf++) {
        #pragma unroll
        for (int nf = 0; nf < NF; nf++) {
            int row = r0 + wm + mf*16 + gr;
            int col = c0 + wn + nf*8 + 2*gc;
            float bx = 0.f, by = 0.f;
            if (bias) { bx = bias[col]; by = bias[col+1]; }
            float2 v0 = make_float2(acc[mf][nf][0] + bx, acc[mf][nf][1] + by);
            float2 v1 = make_float2(acc[mf][nf][2] + bx, acc[mf][nf][3] + by);
            *reinterpret_cast<float2*>(&C[(size_t)row*ldc + col])     = v0;
            *reinterpret_cast<float2*>(&C[(size_t)(row+8)*ldc + col]) = v1;
        }
    }
}

// ---------------- fused edge-LN + attention (R11 version, 3 CTA/SM) ----------------
#define ATTN_SMEM_FLOATS (128*ZP + 2*8*132 + 24)
#define MJ(j) zt[(j)*ZP + 128]
#define RJ(j) zt[(j)*ZP + 129]

__global__ __launch_bounds__(256) void attn_kernel(
        const float* __restrict__ z, const int* __restrict__ mask,
        const float* __restrict__ gz, const float* __restrict__ bz) {
    extern __shared__ float smem[];
    float* zt  = smem;
    float* qa  = zt  + 128*ZP;
    float* sc  = qa  + 8*132;
    float* Ah  = sc  + 8*132;
    float* cqh = Ah  + 8;
    float* sh  = cqh + 8;

    int bi = blockIdx.x, b = bi >> 7;
    int t = threadIdx.x, w = t >> 5, l = t & 31;
    int gr = l >> 2, gc = l & 3;
    int j0 = w * 16;

    {
        unsigned int zt_base = (unsigned int)__cvta_generic_to_shared(zt);
        const float* zb = z + (size_t)bi * 16384;
        #pragma unroll
        for (int k = 0; k < 16; k++) {
            int row = j0 + k;
            cp16(zt_base + (unsigned int)((row*ZP + l*4)*4), zb + row*128 + l*4);
        }
        asm volatile("cp.async.commit_group;\n");
    }

    {
        float4 v = *reinterpret_cast<const float4*>(&g_QKG[(size_t)bi*1024 + w*128 + l*4]);
        uint4 tv = tf4(v);
        *reinterpret_cast<uint4*>(&qa[w*132 + l*4]) = tv;
        float s = __uint_as_float(tv.x) + __uint_as_float(tv.y)
                + __uint_as_float(tv.z) + __uint_as_float(tv.w);
        #pragma unroll
        for (int o = 16; o > 0; o >>= 1) s += __shfl_xor_sync(0xffffffffu, s, o);
        if (l == 0) Ah[w] = s;
    }
    {
        float a = g_Q[(size_t)bi*DS + w*HDIM + l] * g_wkb[w*HDIM + l];
        #pragma unroll
        for (int o = 16; o > 0; o >>= 1) a += __shfl_xor_sync(0xffffffffu, a, o);
        if (l == 0) cqh[w] = a * INV_SCALE;
    }
    __syncthreads();

    asm volatile("cp.async.wait_group 0;\n");
    __syncwarp();

    {
        int jr = j0 + (l >> 1);
        const float* rp = &zt[jr*ZP + (l & 1)*64];
        float s = 0.f, sq = 0.f;
        #pragma unroll
        for (int k = 0; k < 16; k++) {
            float4 v = *reinterpret_cast<const float4*>(rp + 4*k);
            s  += v.x + v.y + v.z + v.w;
            sq += v.x*v.x + v.y*v.y + v.z*v.z + v.w*v.w;
        }
        s  += __shfl_xor_sync(0xffffffffu, s,  1);
        sq += __shfl_xor_sync(0xffffffffu, sq, 1);
        if ((l & 1) == 0) {
            float m = s * (1.0f/128.0f);
            MJ(jr) = m;
            RJ(jr) = rsqrtf(sq * (1.0f/128.0f) - m*m + LN_EPS);
        }
    }
    __syncwarp();

    {
        float acc[4] = {0.f, 0.f, 0.f, 0.f};
        unsigned af[4];
        #pragma unroll
        for (int ks = 0; ks < 16; ks++) {
            int ko = ks * 8;
            af[0] = f2tf(zt[(j0+gr)*ZP   + ko + gc]);
            af[1] = f2tf(zt[(j0+gr+8)*ZP + ko + gc]);
            af[2] = f2tf(zt[(j0+gr)*ZP   + ko + gc + 4]);
            af[3] = f2tf(zt[(j0+gr+8)*ZP + ko + gc + 4]);
            unsigned b0 = __float_as_uint(qa[gr*132 + ko + gc]);
            unsigned b1 = __float_as_uint(qa[gr*132 + ko + gc + 4]);
            mma_tf32(acc, af, b0, b1);
        }
        int jA = j0 + gr, jB = j0 + gr + 8;
        int h0 = 2*gc, h1 = 2*gc + 1;
        const int* mrow = &mask[b*128];
        float aA = (mrow[jA] != 0) ? 0.f : -3.0e38f;
        float aB = (mrow[jB] != 0) ? 0.f : -3.0e38f;
        float rA = RJ(jA), mA = MJ(jA);
        float rB = RJ(jB), mB = MJ(jB);
        float A0 = Ah[h0], A1 = Ah[h1], C0 = cqh[h0], C1 = cqh[h1];
        sc[h0*132 + jA] = rA*(acc[0] - mA*A0) + C0 + aA;
        sc[h1*132 + jA] = rA*(acc[1] - mA*A1) + C1 + aA;
        sc[h0*132 + jB] = rB*(acc[2] - mB*A0) + C0 + aB;
        sc[h1*132 + jB] = rB*(acc[3] - mB*A1) + C1 + aB;
    }
    __syncthreads();

    {
        int h = w;
        float v0 = sc[h*132 + l],      v1 = sc[h*132 + l + 32];
        float v2 = sc[h*132 + l + 64], v3 = sc[h*132 + l + 96];
        float mx = fmaxf(fmaxf(v0, v1), fmaxf(v2, v3));
        #pragma unroll
        for (int o = 16; o > 0; o >>= 1) mx = fmaxf(mx, __shfl_xor_sync(0xffffffffu, mx, o));
        float e0 = expf(v0-mx), e1 = expf(v1-mx), e2 = expf(v2-mx), e3 = expf(v3-mx);
        float s = e0+e1+e2+e3;
        #pragma unroll
        for (int o = 16; o > 0; o >>= 1) s += __shfl_xor_sync(0xffffffffu, s, o);
        float inv = 1.0f / s;
        float w0 = e0*inv*RJ(l),    w1 = e1*inv*RJ(l+32);
        float w2 = e2*inv*RJ(l+64), w3 = e3*inv*RJ(l+96);
        sc[h*132 + l]      = __uint_as_float(f2tf(w0));
        sc[h*132 + l + 32] = __uint_as_float(f2tf(w1));
        sc[h*132 + l + 64] = __uint_as_float(f2tf(w2));
        sc[h*132 + l + 96] = __uint_as_float(f2tf(w3));
        float sm = w0*MJ(l) + w1*MJ(l+32) + w2*MJ(l+64) + w3*MJ(l+96);
        #pragma unroll
        for (int o = 16; o > 0; o >>= 1) sm += __shfl_xor_sync(0xffffffffu, sm, o);
        if (l == 0) sh[h] = sm;
    }
    __syncthreads();

    {
        int d0 = w * 16;
        float acc[4] = {0.f, 0.f, 0.f, 0.f};
        unsigned af[4];
        #pragma unroll
        for (int ks = 0; ks < 16; ks++) {
            int ko = ks * 8;
            af[0] = f2tf(zt[(ko+gc)*ZP   + d0 + gr]);
            af[1] = f2tf(zt[(ko+gc)*ZP   + d0 + gr + 8]);
            af[2] = f2tf(zt[(ko+gc+4)*ZP + d0 + gr]);
            af[3] = f2tf(zt[(ko+gc+4)*ZP + d0 + gr + 8]);
            unsigned b0 = __float_as_uint(sc[gr*132 + ko + gc]);
            unsigned b1 = __float_as_uint(sc[gr*132 + ko + gc + 4]);
            mma_tf32(acc, af, b0, b1);
        }
        int d = d0 + gr, d2 = d + 8;
        int h0 = 2*gc, h1 = h0 + 1;
        float s0 = sh[h0], s1 = sh[h1];
        float gzd = gz[d],  bzd = bz[d];
        float gz2 = gz[d2], bz2 = bz[d2];
        float* cb = &g_CTX[(size_t)bi*1024];
        cb[h0*128 + d]  = gzd*(acc[0] - s0) + bzd;
        cb[h1*128 + d]  = gzd*(acc[1] - s1) + bzd;
        cb[h0*128 + d2] = gz2*(acc[2] - s0) + bz2;
        cb[h1*128 + d2] = gz2*(acc[3] - s1) + bz2;
    }
}

// ---------------- launch ----------------
extern "C" void kernel_launch(void* const* d_in, const int* in_sizes, int n_in,
                              void* d_out, int out_size) {
    const float* z    = (const float*)d_in[0];
    const float* s    = (const float*)d_in[1];
    const int*   mask = (const int*)d_in[2];
    const float* wq   = (const float*)d_in[3];
    const float* bq   = (const float*)d_in[4];
    const float* wk   = (const float*)d_in[5];
    const float* bk   = (const float*)d_in[6];
    const float* wv   = (const float*)d_in[7];
    const float* bv   = (const float*)d_in[8];
    const float* wo   = (const float*)d_in[9];
    const float* bo   = (const float*)d_in[10];
    const float* gz   = (const float*)d_in[11];
    const float* bz   = (const float*)d_in[12];
    const float* gs   = (const float*)d_in[13];
    const float* bs   = (const float*)d_in[14];
    float* out = (float*)d_out;

    const int attn_smem = ATTN_SMEM_FLOATS * (int)sizeof(float);   // 76128 B
    const int gq_smem   = GQ_SMEM_FLOATS * (int)sizeof(float);     // 27904 B
    const int smem3264  = (2*32*36 + 2*64*36) * (int)sizeof(float);
    const int smem3232  = (2*32*36 + 2*32*36) * (int)sizeof(float);
    cudaFuncSetAttribute(attn_kernel, cudaFuncAttributeMaxDynamicSharedMemorySize, attn_smem);
    cudaFuncSetAttribute(attn_kernel, cudaFuncAttributePreferredSharedMemoryCarveout, 100);
    cudaFuncSetAttribute(gemm_q, cudaFuncAttributeMaxDynamicSharedMemorySize, gq_smem);
    cudaFuncSetAttribute(gemm_tc<32,64,2,4>, cudaFuncAttributeMaxDynamicSharedMemorySize, smem3264);
    cudaFuncSetAttribute(gemm_tc<32,32,2,4>, cudaFuncAttributeMaxDynamicSharedMemorySize, smem3232);

    float *Q, *QKG, *CTX, *OUTS, *Wk2;
    cudaGetSymbolAddress((void**)&Q,    g_Q);
    cudaGetSymbolAddress((void**)&QKG,  g_QKG);
    cudaGetSymbolAddress((void**)&CTX,  g_CTX);
    cudaGetSymbolAddress((void**)&OUTS, g_OUTS);
    cudaGetSymbolAddress((void**)&Wk2,  g_Wk2);

    // launch idx:
    pre_kernel<<<129, 256>>>(wk, bk, bz, gz, wq, bq, gs, bs);                                          // 0
    // Q = LN(s) @ wq^T + bq  (LN fused)  grid 256
    gemm_q<<<dim3(4, 64), 256, gq_smem>>>(s, wq, gs);                                                  // 1
    // QKG = Q(head) @ Wk2^T  [2048,1024] K=32   grid 1024
    gemm_tc<32,64,2,4><<<dim3(16,64), 256, smem3264>>>(Q, DS, Wk2, HDIM, nullptr, QKG, Hh*DZ, HDIM, DZ, HDIM); // 2
    // fused attention
    attn_kernel<<<BI, 256, attn_smem>>>(z, mask, gz, bz);                                              // 3  <- profiled
    // OUTS = CTX(head) @ wv^T + bv  [2048,256] K=128  grid 512
    gemm_tc<32,32,2,4><<<dim3(8,64), 256, smem3232>>>(CTX, Hh*DZ, wv, DZ, bv, OUTS, DS, DZ, HDIM, DZ); // 4
    // FINAL = OUTS @ wo^T + bo  [2048,256] K=256  grid 512
    gemm_tc<32,32,2,4><<<dim3(8,64), 256, smem3232>>>(OUTS, DS, wo, DS, bo, out, DS, DS, 1<<30, 0);    // 5
}

// round 16
// speedup vs baseline: 1.2783x; 1.2783x over previous
#include <cuda_runtime.h>
#include <cstdint>
#include <math.h>

#define Bb 16
#define Nn 128
#define DZ 128
#define DS 256
#define Hh 8
#define HDIM 32
#define BI (Bb*Nn)
#define INV_SCALE 0.17677669529663687f
#define LN_EPS 1e-5f
#define ZP 132

// ---------------- scratch ----------------
__device__ __align__(16) float g_SN  [BI*DS];
__device__ __align__(16) float g_Q   [BI*DS];
__device__ __align__(16) float g_QKG [BI*Hh*DZ];
__device__ __align__(16) float g_CTX [BI*Hh*DZ];
__device__ __align__(16) float g_OUTS[BI*DS];
__device__ __align__(16) float g_wkb [DS];
__device__ __align__(16) float g_Wk2 [Hh*DZ*HDIM];   // [o=h*128+d][e]

__device__ __forceinline__ unsigned f2tf(float x) {
    unsigned r; asm("cvt.rna.tf32.f32 %0, %1;" : "=r"(r) : "f"(x)); return r;
}
__device__ __forceinline__ uint4 tf4(float4 v) {
    return make_uint4(f2tf(v.x), f2tf(v.y), f2tf(v.z), f2tf(v.w));
}
__device__ __forceinline__ void mma_tf32(float* c, const unsigned* a, unsigned b0, unsigned b1) {
    asm volatile(
        "mma.sync.aligned.m16n8k8.row.col.f32.tf32.tf32.f32 "
        "{%0,%1,%2,%3}, {%4,%5,%6,%7}, {%8,%9}, {%0,%1,%2,%3};"
        : "+f"(c[0]), "+f"(c[1]), "+f"(c[2]), "+f"(c[3])
        : "r"(a[0]), "r"(a[1]), "r"(a[2]), "r"(a[3]), "r"(b0), "r"(b1));
}
__device__ __forceinline__ void cp16(unsigned int dst, const void* src) {
    asm volatile("cp.async.cg.shared.global [%0], [%1], 16;\n" :: "r"(dst), "l"(src));
}

// ---------------- fused pre: s_query layernorm + weight prep ----------------
__global__ void pre_kernel(const float* __restrict__ s, const float* __restrict__ gs,
                           const float* __restrict__ bs,
                           const float* __restrict__ wk, const float* __restrict__ bk,
                           const float* __restrict__ bz, const float* __restrict__ gz) {
    int t = threadIdx.x;
    if (blockIdx.x < BI) {
        int bi = blockIdx.x;
        float x = s[(size_t)bi*DS + t];
        float sm = x, sq = x*x;
        #pragma unroll
        for (int o = 16; o > 0; o >>= 1) {
            sm += __shfl_xor_sync(0xffffffffu, sm, o);
            sq += __shfl_xor_sync(0xffffffffu, sq, o);
        }
        __shared__ float ps[8], pq[8], mv[2];
        int w = t >> 5, l = t & 31;
        if (l == 0) { ps[w] = sm; pq[w] = sq; }
        __syncthreads();
        if (t == 0) {
            float a = 0.f, b2 = 0.f;
            #pragma unroll
            for (int k = 0; k < 8; k++) { a += ps[k]; b2 += pq[k]; }
            float m = a * (1.0f/DS);
            mv[0] = m;
            mv[1] = rsqrtf(b2 * (1.0f/DS) - m*m + LN_EPS);
        }
        __syncthreads();
        g_SN[(size_t)bi*DS + t] = (x - mv[0]) * mv[1] * gs[t] + bs[t];
    } else {
        int pb = blockIdx.x - BI;
        int idx = pb * 256 + t;
        int o = idx >> 5, e = idx & 31;
        int h = o >> 7,  d = o & 127;
        g_Wk2[idx] = wk[(size_t)(h*HDIM + e)*DZ + d] * gz[d] * INV_SCALE;
        if (pb == 0) {
            int w = t >> 5, l = t & 31;
            for (int r = w; r < DS; r += 8) {
                float a = 0.f;
                #pragma unroll
                for (int k = 0; k < 4; k++) { int dd = l + 32*k; a += wk[(size_t)r*DZ + dd] * bz[dd]; }
                #pragma unroll
                for (int oo = 16; oo > 0; oo >>= 1) a += __shfl_xor_sync(0xffffffffu, a, oo);
                if (l == 0) g_wkb[r] = a + bk[r];
            }
        }
    }
}

// ---------------- tf32 GEMM ----------------
template<int BM, int BN, int WGM, int WGN>
__global__ __launch_bounds__(256) void gemm_tc(
        const float* __restrict__ A, int lda,
        const float* __restrict__ B, int ldb,
        const float* __restrict__ bias,
        float* __restrict__ C, int ldc, int K,
        int head_cols, int ahs) {
    constexpr int TM = BM/WGM, TN = BN/WGN, MF = TM/16, NF = TN/8;
    constexpr int LA = BM*8/256;
    constexpr int LB = BN*8/256;
    extern __shared__ float smem[];
    float* Asb = smem;
    float* Bsb = smem + 2*BM*36;

    int t = threadIdx.x, w = t >> 5, lane = t & 31;
    int gr = lane >> 2, gc = lane & 3;
    int wm = (w / WGN) * TM, wn = (w % WGN) * TN;
    int r0 = blockIdx.y * BM, c0 = blockIdx.x * BN;
    int abase = (c0 / head_cols) * ahs;

    float acc[MF][NF][4];
    #pragma unroll
    for (int mf = 0; mf < MF; mf++)
        #pragma unroll
        for (int nf = 0; nf < NF; nf++)
            #pragma unroll
            for (int q = 0; q < 4; q++) acc[mf][nf][q] = 0.f;

    float4 ra[LA], rb[LB];
    #pragma unroll
    for (int i = 0; i < LA; i++) {
        int idx = t + i*256; int row = idx >> 3, k4 = idx & 7;
        ra[i] = *reinterpret_cast<const float4*>(&A[(size_t)(r0+row)*lda + abase + k4*4]);
    }
    #pragma unroll
    for (int i = 0; i < LB; i++) {
        int idx = t + i*256; int row = idx >> 3, k4 = idx & 7;
        rb[i] = *reinterpret_cast<const float4*>(&B[(size_t)(c0+row)*ldb + k4*4]);
    }
    #pragma unroll
    for (int i = 0; i < LA; i++) {
        int idx = t + i*256; int row = idx >> 3, k4 = idx & 7;
        *reinterpret_cast<uint4*>(&Asb[row*36 + k4*4]) = tf4(ra[i]);
    }
    #pragma unroll
    for (int i = 0; i < LB; i++) {
        int idx = t + i*256; int row = idx >> 3, k4 = idx & 7;
        *reinterpret_cast<uint4*>(&Bsb[row*36 + k4*4]) = tf4(rb[i]);
    }
    __syncthreads();

    int nch = K >> 5;
    for (int ch = 0; ch < nch; ch++) {
        int cur = ch & 1;
        const float* As = Asb + cur*BM*36;
        const float* Bs = Bsb + cur*BN*36;
        if (ch + 1 < nch) {
            int kc = (ch+1)*32;
            #pragma unroll
            for (int i = 0; i < LA; i++) {
                int idx = t + i*256; int row = idx >> 3, k4 = idx & 7;
                ra[i] = *reinterpret_cast<const float4*>(&A[(size_t)(r0+row)*lda + abase + kc + k4*4]);
            }
            #pragma unroll
            for (int i = 0; i < LB; i++) {
                int idx = t + i*256; int row = idx >> 3, k4 = idx & 7;
                rb[i] = *reinterpret_cast<const float4*>(&B[(size_t)(c0+row)*ldb + kc + k4*4]);
            }
        }
        #pragma unroll
        for (int ks = 0; ks < 4; ks++) {
            int ko = ks * 8;
            unsigned af[MF][4];
            #pragma unroll
            for (int mf = 0; mf < MF; mf++) {
                const float* ap = &As[(wm + mf*16 + gr)*36 + ko + gc];
                af[mf][0] = __float_as_uint(ap[0]);
                af[mf][1] = __float_as_uint(ap[8*36]);
                af[mf][2] = __float_as_uint(ap[4]);
                af[mf][3] = __float_as_uint(ap[8*36 + 4]);
            }
            #pragma unroll
            for (int nf = 0; nf < NF; nf++) {
                const float* bp = &Bs[(wn + nf*8 + gr)*36 + ko + gc];
                unsigned b0 = __float_as_uint(bp[0]), b1 = __float_as_uint(bp[4]);
                #pragma unroll
                for (int mf = 0; mf < MF; mf++)
                    mma_tf32(acc[mf][nf], af[mf], b0, b1);
            }
        }
        if (ch + 1 < nch) {
            int nxt = cur ^ 1;
            float* Asn = Asb + nxt*BM*36;
            float* Bsn = Bsb + nxt*BN*36;
            #pragma unroll
            for (int i = 0; i < LA; i++) {
                int idx = t + i*256; int row = idx >> 3, k4 = idx & 7;
                *reinterpret_cast<uint4*>(&Asn[row*36 + k4*4]) = tf4(ra[i]);
            }
            #pragma unroll
            for (int i = 0; i < LB; i++) {
                int idx = t + i*256; int row = idx >> 3, k4 = idx & 7;
                *reinterpret_cast<uint4*>(&Bsn[row*36 + k4*4]) = tf4(rb[i]);
            }
            __syncthreads();
        }
    }

    #pragma unroll
    for (int mf = 0; mf < MF; mf++) {
        #pragma unroll
        for (int nf = 0; nf < NF; nf++) {
            int row = r0 + wm + mf*16 + gr;
            int col = c0 + wn + nf*8 + 2*gc;
            float bx = 0.f, by = 0.f;
            if (bias) { bx = bias[col]; by = bias[col+1]; }
            float2 v0 = make_float2(acc[mf][nf][0] + bx, acc[mf][nf][1] + by);
            float2 v1 = make_float2(acc[mf][nf][2] + bx, acc[mf][nf][3] + by);
            *reinterpret_cast<float2*>(&C[(size_t)row*ldc + col])     = v0;
            *reinterpret_cast<float2*>(&C[(size_t)(row+8)*ldc + col]) = v1;
        }
    }
}

// ---------------- fused edge-LN + attention (warp-private z rows, 3 CTA/SM) ----------------
#define ATTN_SMEM_FLOATS (128*ZP + 2*8*132 + 24)
#define MJ(j) zt[(j)*ZP + 128]
#define RJ(j) zt[(j)*ZP + 129]

__global__ __launch_bounds__(256) void attn_kernel(
        const float* __restrict__ z, const int* __restrict__ mask,
        const float* __restrict__ gz, const float* __restrict__ bz) {
    extern __shared__ float smem[];
    float* zt  = smem;                 // raw fp32 z tile (+LN stats in padding)
    float* qa  = zt  + 128*ZP;         // tf32 qkg
    float* sc  = qa  + 8*132;          // scores -> tf32 weights
    float* Ah  = sc  + 8*132;
    float* cqh = Ah  + 8;
    float* sh  = cqh + 8;

    int bi = blockIdx.x, b = bi >> 7;
    int t = threadIdx.x, w = t >> 5, l = t & 31;
    int gr = l >> 2, gc = l & 3;
    int j0 = w * 16;

    // 1) warp-private z copies: warp w copies rows [16w, 16w+16)
    {
        unsigned int zt_base = (unsigned int)__cvta_generic_to_shared(zt);
        const float* zb = z + (size_t)bi * 16384;
        #pragma unroll
        for (int k = 0; k < 16; k++) {
            int row = j0 + k;
            cp16(zt_base + (unsigned int)((row*ZP + l*4)*4), zb + row*128 + l*4);
        }
        asm volatile("cp.async.commit_group;\n");
    }

    // 2) overlap: qa (tf32) + Ah; cq fold from Q . wkb
    {
        float4 v = *reinterpret_cast<const float4*>(&g_QKG[(size_t)bi*1024 + w*128 + l*4]);
        uint4 tv = tf4(v);
        *reinterpret_cast<uint4*>(&qa[w*132 + l*4]) = tv;
        float s = __uint_as_float(tv.x) + __uint_as_float(tv.y)
                + __uint_as_float(tv.z) + __uint_as_float(tv.w);
        #pragma unroll
        for (int o = 16; o > 0; o >>= 1) s += __shfl_xor_sync(0xffffffffu, s, o);
        if (l == 0) Ah[w] = s;
    }
    {
        float a = g_Q[(size_t)bi*DS + w*HDIM + l] * g_wkb[w*HDIM + l];
        #pragma unroll
        for (int o = 16; o > 0; o >>= 1) a += __shfl_xor_sync(0xffffffffu, a, o);
        if (l == 0) cqh[w] = a * INV_SCALE;
    }
    __syncthreads();   // publish qa/Ah/cqh

    // 3) wait own z rows only (warp-local)
    asm volatile("cp.async.wait_group 0;\n");
    __syncwarp();

    // 4) LN stats for own rows: lane pair per row -> stats into zt row padding
    {
        int jr = j0 + (l >> 1);
        const float* rp = &zt[jr*ZP + (l & 1)*64];
        float s = 0.f, sq = 0.f;
        #pragma unroll
        for (int k = 0; k < 16; k++) {
            float4 v = *reinterpret_cast<const float4*>(rp + 4*k);
            s  += v.x + v.y + v.z + v.w;
            sq += v.x*v.x + v.y*v.y + v.z*v.z + v.w*v.w;
        }
        s  += __shfl_xor_sync(0xffffffffu, s,  1);
        sq += __shfl_xor_sync(0xffffffffu, sq, 1);
        if ((l & 1) == 0) {
            float m = s * (1.0f/128.0f);
            MJ(jr) = m;
            RJ(jr) = rsqrtf(sq * (1.0f/128.0f) - m*m + LN_EPS);
        }
    }
    __syncwarp();

    // 5) scores MMA for own rows
    {
        float acc[4] = {0.f, 0.f, 0.f, 0.f};
        unsigned af[4];
        #pragma unroll
        for (int ks = 0; ks < 16; ks++) {
            int ko = ks * 8;
            af[0] = f2tf(zt[(j0+gr)*ZP   + ko + gc]);
            af[1] = f2tf(zt[(j0+gr+8)*ZP + ko + gc]);
            af[2] = f2tf(zt[(j0+gr)*ZP   + ko + gc + 4]);
            af[3] = f2tf(zt[(j0+gr+8)*ZP + ko + gc + 4]);
            unsigned b0 = __float_as_uint(qa[gr*132 + ko + gc]);
            unsigned b1 = __float_as_uint(qa[gr*132 + ko + gc + 4]);
            mma_tf32(acc, af, b0, b1);
        }
        int jA = j0 + gr, jB = j0 + gr + 8;
        int h0 = 2*gc, h1 = 2*gc + 1;
        const int* mrow = &mask[b*128];
        float aA = (mrow[jA] != 0) ? 0.f : -3.0e38f;
        float aB = (mrow[jB] != 0) ? 0.f : -3.0e38f;
        float rA = RJ(jA), mA = MJ(jA);
        float rB = RJ(jB), mB = MJ(jB);
        float A0 = Ah[h0], A1 = Ah[h1], C0 = cqh[h0], C1 = cqh[h1];
        sc[h0*132 + jA] = rA*(acc[0] - mA*A0) + C0 + aA;
        sc[h1*132 + jA] = rA*(acc[1] - mA*A1) + C1 + aA;
        sc[h0*132 + jB] = rB*(acc[2] - mB*A0) + C0 + aB;
        sc[h1*132 + jB] = rB*(acc[3] - mB*A1) + C1 + aB;
    }
    __syncthreads();

    // 6) softmax per head; sc becomes aw = attn*r (tf32); sh[h] = sum_j aw*m
    {
        int h = w;
        float v0 = sc[h*132 + l],      v1 = sc[h*132 + l + 32];
        float v2 = sc[h*132 + l + 64], v3 = sc[h*132 + l + 96];
        float mx = fmaxf(fmaxf(v0, v1), fmaxf(v2, v3));
        #pragma unroll
        for (int o = 16; o > 0; o >>= 1) mx = fmaxf(mx, __shfl_xor_sync(0xffffffffu, mx, o));
        float e0 = expf(v0-mx), e1 = expf(v1-mx), e2 = expf(v2-mx), e3 = expf(v3-mx);
        float s = e0+e1+e2+e3;
        #pragma unroll
        for (int o = 16; o > 0; o >>= 1) s += __shfl_xor_sync(0xffffffffu, s, o);
        float inv = 1.0f / s;
        float w0 = e0*inv*RJ(l),    w1 = e1*inv*RJ(l+32);
        float w2 = e2*inv*RJ(l+64), w3 = e3*inv*RJ(l+96);
        sc[h*132 + l]      = __uint_as_float(f2tf(w0));
        sc[h*132 + l + 32] = __uint_as_float(f2tf(w1));
        sc[h*132 + l + 64] = __uint_as_float(f2tf(w2));
        sc[h*132 + l + 96] = __uint_as_float(f2tf(w3));
        float sm = w0*MJ(l) + w1*MJ(l+32) + w2*MJ(l+64) + w3*MJ(l+96);
        #pragma unroll
        for (int o = 16; o > 0; o >>= 1) sm += __shfl_xor_sync(0xffffffffu, sm, o);
        if (l == 0) sh[h] = sm;
    }
    __syncthreads();

    // 7) ctx MMA + direct epilogue
    {
        int d0 = w * 16;
        float acc[4] = {0.f, 0.f, 0.f, 0.f};
        unsigned af[4];
        #pragma unroll
        for (int ks = 0; ks < 16; ks++) {
            int ko = ks * 8;
            af[0] = f2tf(zt[(ko+gc)*ZP   + d0 + gr]);
            af[1] = f2tf(zt[(ko+gc)*ZP   + d0 + gr + 8]);
            af[2] = f2tf(zt[(ko+gc+4)*ZP + d0 + gr]);
            af[3] = f2tf(zt[(ko+gc+4)*ZP + d0 + gr + 8]);
            unsigned b0 = __float_as_uint(sc[gr*132 + ko + gc]);
            unsigned b1 = __float_as_uint(sc[gr*132 + ko + gc + 4]);
            mma_tf32(acc, af, b0, b1);
        }
        int d = d0 + gr, d2 = d + 8;
        int h0 = 2*gc, h1 = h0 + 1;
        float s0 = sh[h0], s1 = sh[h1];
        float gzd = gz[d],  bzd = bz[d];
        float gz2 = gz[d2], bz2 = bz[d2];
        float* cb = &g_CTX[(size_t)bi*1024];
        cb[h0*128 + d]  = gzd*(acc[0] - s0) + bzd;
        cb[h1*128 + d]  = gzd*(acc[1] - s1) + bzd;
        cb[h0*128 + d2] = gz2*(acc[2] - s0) + bz2;
        cb[h1*128 + d2] = gz2*(acc[3] - s1) + bz2;
    }
}

// ---------------- launch ----------------
extern "C" void kernel_launch(void* const* d_in, const int* in_sizes, int n_in,
                              void* d_out, int out_size) {
    const float* z    = (const float*)d_in[0];
    const float* s    = (const float*)d_in[1];
    const int*   mask = (const int*)d_in[2];
    const float* wq   = (const float*)d_in[3];
    const float* bq   = (const float*)d_in[4];
    const float* wk   = (const float*)d_in[5];
    const float* bk   = (const float*)d_in[6];
    const float* wv   = (const float*)d_in[7];
    const float* bv   = (const float*)d_in[8];
    const float* wo   = (const float*)d_in[9];
    const float* bo   = (const float*)d_in[10];
    const float* gz   = (const float*)d_in[11];
    const float* bz   = (const float*)d_in[12];
    const float* gs   = (const float*)d_in[13];
    const float* bs   = (const float*)d_in[14];
    float* out = (float*)d_out;

    const int attn_smem = ATTN_SMEM_FLOATS * (int)sizeof(float);   // 76128 B
    const int smem64    = (2*64*36 + 2*64*36) * (int)sizeof(float);
    const int smem6432  = (2*64*36 + 2*32*36) * (int)sizeof(float);
    const int smem3264  = (2*32*36 + 2*64*36) * (int)sizeof(float);
    cudaFuncSetAttribute(attn_kernel, cudaFuncAttributeMaxDynamicSharedMemorySize, attn_smem);
    cudaFuncSetAttribute(attn_kernel, cudaFuncAttributePreferredSharedMemoryCarveout, 100);
    cudaFuncSetAttribute(gemm_tc<64,64,2,4>, cudaFuncAttributeMaxDynamicSharedMemorySize, smem64);
    cudaFuncSetAttribute(gemm_tc<64,32,4,2>, cudaFuncAttributeMaxDynamicSharedMemorySize, smem6432);
    cudaFuncSetAttribute(gemm_tc<32,64,2,4>, cudaFuncAttributeMaxDynamicSharedMemorySize, smem3264);

    float *SN, *Q, *QKG, *CTX, *OUTS, *Wk2;
    cudaGetSymbolAddress((void**)&SN,   g_SN);
    cudaGetSymbolAddress((void**)&Q,    g_Q);
    cudaGetSymbolAddress((void**)&QKG,  g_QKG);
    cudaGetSymbolAddress((void**)&CTX,  g_CTX);
    cudaGetSymbolAddress((void**)&OUTS, g_OUTS);
    cudaGetSymbolAddress((void**)&Wk2,  g_Wk2);

    // launch idx:
    pre_kernel<<<BI + 128, 256>>>(s, gs, bs, wk, bk, bz, gz);                                          // 0
    gemm_tc<32,64,2,4><<<dim3(4,64), 256, smem3264>>>(SN, DS, wq, DS, bq, Q, DS, DS, 1<<30, 0);        // 1
    gemm_tc<64,64,2,4><<<dim3(16,32), 256, smem64>>>(Q, DS, Wk2, HDIM, nullptr, QKG, Hh*DZ, HDIM, DZ, HDIM); // 2
    attn_kernel<<<BI, 256, attn_smem>>>(z, mask, gz, bz);                                              // 3  <- profiled
    gemm_tc<64,32,4,2><<<dim3(8,32), 256, smem6432>>>(CTX, Hh*DZ, wv, DZ, bv, OUTS, DS, DZ, HDIM, DZ); // 4
    gemm_tc<32,64,2,4><<<dim3(4,64), 256, smem3264>>>(OUTS, DS, wo, DS, bo, out, DS, DS, 1<<30, 0);    // 5
}